// round 12
// baseline (speedup 1.0000x reference)
#include <cuda_runtime.h>
#include <cuda_fp16.h>
#include <cstdint>

#define NB 512   // batch
#define DD 512   // embed dim
#define OD 512   // out dim

// -------- scratch (no cudaMalloc allowed) --------
__device__ float g_h[NB * DD];
__device__ float g_logits[NB * DD];
__device__ float g_textw[NB * DD];
__device__ float g_outx[NB * DD];
__device__ float g_gate[NB * DD];
__device__ float g_tmp[NB * DD];
__device__ __half g_outxh[NB * DD];  // fp16 copy of outx
__device__ __half g_WoT[OD * DD];    // WoT[o][d] = fp16(Wo[d][o])

// ============================================================
// Helpers (plain sm_80+ PTX: mma.sync / ldmatrix / cp.async)
// ============================================================
__device__ __forceinline__ uint32_t smem_u32(const void* p) {
    uint32_t a;
    asm("{ .reg .u64 t; cvta.to.shared.u64 t, %1; cvt.u32.u64 %0, t; }"
        : "=r"(a) : "l"(p));
    return a;
}

#define CP_ASYNC_16(dst, src) \
    asm volatile("cp.async.cg.shared.global [%0], [%1], 16;" \
                 :: "r"((uint32_t)(dst)), "l"(src))
#define CP_ASYNC_COMMIT() asm volatile("cp.async.commit_group;" ::: "memory")
#define CP_ASYNC_WAIT0()  asm volatile("cp.async.wait_group 0;" ::: "memory")

__device__ __forceinline__ void ldsm_x4(uint32_t r[4], uint32_t addr) {
    asm volatile("ldmatrix.sync.aligned.m8n8.x4.shared.b16 {%0,%1,%2,%3}, [%4];"
                 : "=r"(r[0]), "=r"(r[1]), "=r"(r[2]), "=r"(r[3]) : "r"(addr));
}

// fp16 x fp16 -> fp16 accumulate (rate experiment: possibly 2x the f32-acc rate)
__device__ __forceinline__ void mma_fp16_acc16(uint32_t c[2], const uint32_t a[4],
                                               const uint32_t b0, const uint32_t b1) {
    asm volatile(
        "mma.sync.aligned.m16n8k16.row.col.f16.f16.f16.f16 "
        "{%0,%1}, {%2,%3,%4,%5}, {%6,%7}, {%0,%1};"
        : "+r"(c[0]), "+r"(c[1])
        : "r"(a[0]), "r"(a[1]), "r"(a[2]), "r"(a[3]), "r"(b0), "r"(b1));
}

// ============================================================
// smem layout for big kernel (dynamic)
//   gate row (fp32): 2048 B
//   K-chunk = 64: rows hold 64 fp16 = 128B data + 16B pad -> stride 144
//   2 buffers, each: A(128x144=18432) B(128x144=18432) = 36864 B
// ============================================================
#define ASTRIDE 144
#define OFF_A 0
#define OFF_B 18432
#define BUF_BYTES 36864
#define SMEM_BYTES (2048 + 2 * BUF_BYTES)   // 75776

// ============================================================
// Preamble small GEMM core (software-pipelined, from R11)
// ============================================================
template <int ACT, bool WRITE_H>
__device__ __forceinline__ void gemm_small_body(
    const float* __restrict__ A, const float* __restrict__ W,
    const float* __restrict__ bias, float* __restrict__ C,
    __half* __restrict__ Ch, int m0, int n0)
{
    __shared__ float As[16][64];
    __shared__ float Bs[16][32];
    const int t = threadIdx.x;
    const int tx = t & 7, ty = t >> 3;
    const int am = t >> 1, akq = (t & 1) * 8;
    const int bk = t >> 3, bn = (t & 7) * 4;

    float4 ra0, ra1, rb;
    auto ldgTiles = [&](int k0) {
        ra0 = __ldg((const float4*)&A[(size_t)(m0 + am) * DD + k0 + akq]);
        ra1 = __ldg((const float4*)&A[(size_t)(m0 + am) * DD + k0 + akq + 4]);
        rb  = __ldg((const float4*)&W[(size_t)(k0 + bk) * OD + n0 + bn]);
    };

    float acc[4][4] = {};
    ldgTiles(0);

    for (int it = 0; it < 32; it++) {
        if (it) __syncthreads();
        As[akq + 0][am] = ra0.x; As[akq + 1][am] = ra0.y;
        As[akq + 2][am] = ra0.z; As[akq + 3][am] = ra0.w;
        As[akq + 4][am] = ra1.x; As[akq + 5][am] = ra1.y;
        As[akq + 6][am] = ra1.z; As[akq + 7][am] = ra1.w;
        *(float4*)&Bs[bk][bn] = rb;
        __syncthreads();
        if (it < 31) ldgTiles((it + 1) * 16);

        #pragma unroll
        for (int k = 0; k < 16; k++) {
            float a[4], b[4];
            *(float4*)a = *(const float4*)&As[k][ty * 4];
            *(float4*)b = *(const float4*)&Bs[k][tx * 4];
            #pragma unroll
            for (int r = 0; r < 4; r++)
                #pragma unroll
                for (int c = 0; c < 4; c++)
                    acc[r][c] += a[r] * b[c];
        }
    }

    #pragma unroll
    for (int r = 0; r < 4; r++) {
        const int m = m0 + ty * 4 + r;
        float4 v; float* vv = (float*)&v;
        #pragma unroll
        for (int c = 0; c < 4; c++) {
            float x = acc[r][c] + __ldg(&bias[n0 + tx * 4 + c]);
            if (ACT == 1) x = fmaxf(x, 0.0f);
            if (ACT == 2) x = 1.0f / (1.0f + __expf(-x));
            vv[c] = x;
        }
        *(float4*)&C[(size_t)m * OD + n0 + tx * 4] = v;
        if (WRITE_H) {
            __half2 p0 = __float22half2_rn(make_float2(v.x, v.y));
            __half2 p1 = __float22half2_rn(make_float2(v.z, v.w));
            *(uint2*)&Ch[(size_t)m * OD + n0 + tx * 4] =
                make_uint2(*(uint32_t*)&p0, *(uint32_t*)&p1);
        }
    }
}

template <int ACT>
__global__ void __launch_bounds__(128)
gemm_small_kernel(const float* __restrict__ A, const float* __restrict__ W,
                  const float* __restrict__ bias, float* __restrict__ C)
{
    gemm_small_body<ACT, false>(A, W, bias, C, nullptr, blockIdx.y * 64, blockIdx.x * 32);
}

__global__ void __launch_bounds__(128)
pre_fused_kernel(const float* __restrict__ text, const float* __restrict__ image,
                 const float* __restrict__ Wa1, const float* __restrict__ ba1,
                 const float* __restrict__ Wx,  const float* __restrict__ bx,
                 float* __restrict__ h, float* __restrict__ outx,
                 __half* __restrict__ outxh)
{
    if (blockIdx.z == 0)
        gemm_small_body<1, false>(text, Wa1, ba1, h, nullptr, blockIdx.y * 64, blockIdx.x * 32);
    else
        gemm_small_body<0, true>(image, Wx, bx, outx, outxh, blockIdx.y * 64, blockIdx.x * 32);
}

// ============================================================
// Preamble: row softmax * text
// ============================================================
__global__ void __launch_bounds__(512)
softmax_mul_kernel(const float* __restrict__ logits, const float* __restrict__ text,
                   float* __restrict__ out)
{
    __shared__ float sdata[512];
    const int row = blockIdx.x, t = threadIdx.x;
    const float v = logits[(size_t)row * DD + t];
    sdata[t] = v; __syncthreads();
    for (int s = 256; s > 0; s >>= 1) { if (t < s) sdata[t] = fmaxf(sdata[t], sdata[t + s]); __syncthreads(); }
    const float mx = sdata[0]; __syncthreads();
    const float e = __expf(v - mx);
    sdata[t] = e; __syncthreads();
    for (int s = 256; s > 0; s >>= 1) { if (t < s) sdata[t] += sdata[t + s]; __syncthreads(); }
    out[(size_t)row * DD + t] = e * (1.0f / sdata[0]) * text[(size_t)row * DD + t];
}

// ============================================================
// Preamble: transpose Wo -> fp16
// ============================================================
__global__ void __launch_bounds__(256)
transpose_wo_h(const float* __restrict__ Wo, __half* __restrict__ T)
{
    __shared__ float tile[32][33];
    const int bo = blockIdx.x * 32;
    const int bd = blockIdx.y * 32;
    const int x = threadIdx.x, y = threadIdx.y;
    #pragma unroll
    for (int r = 0; r < 4; r++)
        tile[y + 8 * r][x] = Wo[(size_t)(bd + y + 8 * r) * OD + bo + x];
    __syncthreads();
    #pragma unroll
    for (int r = 0; r < 4; r++) {
        const int o = bo + y + 8 * r;
        const int d = bd + x;
        T[(size_t)o * DD + d] = __float2half_rn(tile[x][y + 8 * r]);
    }
}

__global__ void mul_kernel(const float* __restrict__ a, const float* __restrict__ b,
                           float* __restrict__ c, int n)
{
    int idx = blockIdx.x * blockDim.x + threadIdx.x;
    if (idx < n) c[idx] = a[idx] * b[idx];
}

// ============================================================
// Big einsum, fp16 HMMA with FP16 ACCUMULATORS (rate experiment)
//   + per-K64-chunk promotion to fp32 registers.
// grid (4 o-tiles, 4 j-tiles, 512 i) = 8192 CTAs, 256 threads (8 warps).
// CTA tile 128(j) x 128(o); warp tile 32x64 (warp_m = wid&3, warp_n = wid>>2).
// ============================================================
__global__ void __launch_bounds__(256, 1)
big_einsum_hmma_kernel(const __half* __restrict__ outxh, const float* __restrict__ gate,
                       const float* __restrict__ bo, float* __restrict__ out)
{
    extern __shared__ char dynsmem[];
    float* gs = (float*)dynsmem;
    const uint32_t sbase = smem_u32(dynsmem) + 2048u;

    const int i  = blockIdx.z;
    const int j0 = blockIdx.y * 128;
    const int o0 = blockIdx.x * 128;
    const int tid  = threadIdx.x;
    const int wid  = tid >> 5;
    const int lane = tid & 31;
    const int warp_m = wid & 3;     // 4 x 32 rows (j)
    const int warp_n = wid >> 2;    // 2 x 64 cols (o)

    gs[tid]       = gate[(size_t)i * DD + tid];
    gs[tid + 256] = gate[(size_t)i * DD + tid + 256];

    const int arow = tid >> 1;
    const int ach  = (tid & 1) * 32;

    auto cpB = [&](int c, int buf) {
        const int c0 = c * 64;
        const uint32_t bdst = sbase + buf * BUF_BYTES + OFF_B;
        #pragma unroll
        for (int q = 0; q < 4; q++) {
            const int g   = tid + q * 256;      // 0..1023
            const int row = g >> 3;             // 0..127
            const int ck  = g & 7;
            const uint32_t dso = (uint32_t)(row * ASTRIDE + ck * 16);
            const __half* src = g_WoT + (size_t)(o0 + row) * DD + c0 + ck * 8;
            CP_ASYNC_16(bdst + dso, src);
        }
        CP_ASYNC_COMMIT();
    };

    uint4 av[4];
    auto loadA = [&](int c) {
        const __half* p = outxh + (size_t)(j0 + arow) * DD + c * 64 + ach;
        #pragma unroll
        for (int q = 0; q < 4; q++) av[q] = __ldg((const uint4*)(p + q * 8));
    };

    auto storeA = [&](int c, int buf) {
        const int d0 = c * 64 + ach;
        const uint32_t ad = sbase + buf * BUF_BYTES + OFF_A + arow * ASTRIDE + ach * 2;
        #pragma unroll
        for (int h = 0; h < 4; h++) {
            const __half2* xa = (const __half2*)&av[h];
            uint32_t w[4];
            #pragma unroll
            for (int q = 0; q < 4; q++) {
                float2 xf = __half22float2(xa[q]);
                const float2 gf = *(const float2*)&gs[d0 + h * 8 + q * 2];
                __half2 r = __float22half2_rn(make_float2(xf.x * gf.x, xf.y * gf.y));
                w[q] = *(uint32_t*)&r;
            }
            asm volatile("st.shared.v4.b32 [%0], {%1,%2,%3,%4};"
                         :: "r"(ad + h * 16), "r"(w[0]), "r"(w[1]), "r"(w[2]), "r"(w[3]));
        }
    };

    const uint32_t a_lane = (uint32_t)(((lane & 7) + ((lane >> 3) & 1) * 8) * ASTRIDE
                                       + (lane >> 4) * 16);
    const uint32_t b_lane = (uint32_t)(((lane & 7) + (lane >> 4) * 8) * ASTRIDE
                                       + ((lane >> 3) & 1) * 16);
    const uint32_t a_warp = (uint32_t)(warp_m * 32 * ASTRIDE);
    const uint32_t b_warp = (uint32_t)(warp_n * 64 * ASTRIDE);

    float    facc[2][8][4] = {};   // fp32 master accumulators
    uint32_t hacc[2][8][2];        // fp16x2 chunk accumulators

    loadA(0);
    cpB(0, 0);
    __syncthreads();
    storeA(0, 0);
    CP_ASYNC_WAIT0();
    __syncthreads();

    for (int c = 0; c < 8; c++) {
        const int buf = c & 1;
        if (c < 7) { loadA(c + 1); cpB(c + 1, buf ^ 1); }

        // zero fp16 chunk accumulators
        #pragma unroll
        for (int mt = 0; mt < 2; mt++)
            #pragma unroll
            for (int g = 0; g < 8; g++) { hacc[mt][g][0] = 0u; hacc[mt][g][1] = 0u; }

        const uint32_t bb = sbase + buf * BUF_BYTES;
        #pragma unroll
        for (int ks = 0; ks < 4; ks++) {
            uint32_t ah[2][4];
            ldsm_x4(ah[0], bb + OFF_A + a_warp + a_lane + ks * 32);
            ldsm_x4(ah[1], bb + OFF_A + a_warp + a_lane + 16 * ASTRIDE + ks * 32);
            #pragma unroll
            for (int g = 0; g < 4; g++) {
                uint32_t bh[4];
                ldsm_x4(bh, bb + OFF_B + b_warp + b_lane + g * 16 * ASTRIDE + ks * 32);
                #pragma unroll
                for (int mt = 0; mt < 2; mt++) {
                    mma_fp16_acc16(hacc[mt][g * 2],     ah[mt], bh[0], bh[1]);
                    mma_fp16_acc16(hacc[mt][g * 2 + 1], ah[mt], bh[2], bh[3]);
                }
            }
        }

        // promote chunk partials to fp32
        #pragma unroll
        for (int mt = 0; mt < 2; mt++)
            #pragma unroll
            for (int g = 0; g < 8; g++) {
                float2 f0 = __half22float2(*(const __half2*)&hacc[mt][g][0]);
                float2 f1 = __half22float2(*(const __half2*)&hacc[mt][g][1]);
                facc[mt][g][0] += f0.x; facc[mt][g][1] += f0.y;
                facc[mt][g][2] += f1.x; facc[mt][g][3] += f1.y;
            }

        if (c < 7) {
            storeA(c + 1, buf ^ 1);
            CP_ASYNC_WAIT0();
            __syncthreads();
        }
    }

    // ---- epilogue: bias + store ----
    const int colb = o0 + warp_n * 64 + (lane & 3) * 2;
    float2 bv[8];
    #pragma unroll
    for (int nj = 0; nj < 8; nj++)
        bv[nj] = __ldg((const float2*)&bo[colb + nj * 8]);

    const int rowb = j0 + warp_m * 32 + (lane >> 2);
    #pragma unroll
    for (int mt = 0; mt < 2; mt++) {
        #pragma unroll
        for (int h = 0; h < 2; h++) {
            const size_t rbase = ((size_t)i * NB + (rowb + mt * 16 + h * 8)) * OD;
            #pragma unroll
            for (int nj = 0; nj < 8; nj++) {
                float2 v;
                v.x = facc[mt][nj][h * 2]     + bv[nj].x;
                v.y = facc[mt][nj][h * 2 + 1] + bv[nj].y;
                *(float2*)&out[rbase + colb + nj * 8] = v;
            }
        }
    }
}

// ============================================================
// kernel_launch
// ============================================================
extern "C" void kernel_launch(void* const* d_in, const int* in_sizes, int n_in,
                              void* d_out, int out_size)
{
    const float* image = (const float*)d_in[0];
    const float* text  = (const float*)d_in[1];
    const float* Wx  = (const float*)d_in[3];
    const float* bx  = (const float*)d_in[4];
    const float* Wy  = (const float*)d_in[5];
    const float* by  = (const float*)d_in[6];
    const float* Wo  = (const float*)d_in[7];
    const float* bo  = (const float*)d_in[8];
    const float* Wa1 = (const float*)d_in[9];
    const float* ba1 = (const float*)d_in[10];
    const float* Wa2 = (const float*)d_in[11];
    const float* ba2 = (const float*)d_in[12];
    float* out = (float*)d_out;

    float *h, *logits, *textw, *outx, *gate, *tmp;
    __half *wot, *outxh;
    cudaGetSymbolAddress((void**)&h,      g_h);
    cudaGetSymbolAddress((void**)&logits, g_logits);
    cudaGetSymbolAddress((void**)&textw,  g_textw);
    cudaGetSymbolAddress((void**)&outx,   g_outx);
    cudaGetSymbolAddress((void**)&gate,   g_gate);
    cudaGetSymbolAddress((void**)&tmp,    g_tmp);
    cudaGetSymbolAddress((void**)&wot,    g_WoT);
    cudaGetSymbolAddress((void**)&outxh,  g_outxh);

    cudaFuncSetAttribute(big_einsum_hmma_kernel,
                         cudaFuncAttributeMaxDynamicSharedMemorySize, SMEM_BYTES);

    const dim3 gsm(OD / 32, NB / 64);   // (16, 8) = 128 CTAs

    transpose_wo_h<<<dim3(16, 16), dim3(32, 8)>>>(Wo, wot);
    pre_fused_kernel<<<dim3(OD / 32, NB / 64, 2), 128>>>(text, image, Wa1, ba1, Wx, bx,
                                                         h, outx, outxh);
    gemm_small_kernel<0><<<gsm, 128>>>(h, Wa2, ba2, logits);
    softmax_mul_kernel<<<NB, 512>>>(logits, text, textw);
    gemm_small_kernel<2><<<gsm, 128>>>(textw, Wy, by, gate);

    if (out_size == NB * NB * OD) {
        dim3 grid(OD / 128, NB / 128, NB);   // (4, 4, 512)
        big_einsum_hmma_kernel<<<grid, 256, SMEM_BYTES>>>(outxh, gate, bo, out);
    } else {
        mul_kernel<<<(NB * DD + 255) / 256, 256>>>(gate, outx, tmp, NB * DD);
        gemm_small_kernel<0><<<gsm, 128>>>(tmp, Wo, bo, out);
    }
}

// round 13
// speedup vs baseline: 1.2974x; 1.2974x over previous
#include <cuda_runtime.h>
#include <cuda_fp16.h>
#include <cstdint>

#define NB 512   // batch
#define DD 512   // embed dim
#define OD 512   // out dim

// -------- scratch (no cudaMalloc allowed) --------
__device__ float g_h[NB * DD];
__device__ float g_logits[NB * DD];
__device__ float g_textw[NB * DD];
__device__ float g_outx[NB * DD];
__device__ float g_gate[NB * DD];
__device__ float g_tmp[NB * DD];
__device__ __half g_outxh[NB * DD];  // fp16 copy of outx
__device__ __half g_WoT[OD * DD];    // WoT[o][d] = fp16(Wo[d][o])

// ============================================================
// Helpers (plain sm_80+ PTX: mma.sync / ldmatrix / cp.async)
// ============================================================
__device__ __forceinline__ uint32_t smem_u32(const void* p) {
    uint32_t a;
    asm("{ .reg .u64 t; cvta.to.shared.u64 t, %1; cvt.u32.u64 %0, t; }"
        : "=r"(a) : "l"(p));
    return a;
}

#define CP_ASYNC_16(dst, src) \
    asm volatile("cp.async.cg.shared.global [%0], [%1], 16;" \
                 :: "r"((uint32_t)(dst)), "l"(src))
#define CP_ASYNC_COMMIT() asm volatile("cp.async.commit_group;" ::: "memory")
#define CP_ASYNC_WAIT0()  asm volatile("cp.async.wait_group 0;" ::: "memory")

__device__ __forceinline__ void ldsm_x4(uint32_t r[4], uint32_t addr) {
    asm volatile("ldmatrix.sync.aligned.m8n8.x4.shared.b16 {%0,%1,%2,%3}, [%4];"
                 : "=r"(r[0]), "=r"(r[1]), "=r"(r[2]), "=r"(r[3]) : "r"(addr));
}

__device__ __forceinline__ void mma_fp16(float c[4], const uint32_t a[4],
                                         const uint32_t b0, const uint32_t b1) {
    asm volatile(
        "mma.sync.aligned.m16n8k16.row.col.f32.f16.f16.f32 "
        "{%0,%1,%2,%3}, {%4,%5,%6,%7}, {%8,%9}, {%0,%1,%2,%3};"
        : "+f"(c[0]), "+f"(c[1]), "+f"(c[2]), "+f"(c[3])
        : "r"(a[0]), "r"(a[1]), "r"(a[2]), "r"(a[3]), "r"(b0), "r"(b1));
}

// ============================================================
// smem layout for big kernel (dynamic) — R10/R11 best structure
//   gate rows (fp32, 2 i): 4096 B
//   K-chunk = 64: rows hold 64 fp16 = 128B data + 16B pad -> stride 144
//   2 buffers, each: A0(18432) A1(18432) B(128x144=18432) = 55296 B
// ============================================================
#define ASTRIDE 144
#define OFF_A0 0
#define OFF_A1 18432
#define OFF_B  36864
#define BUF_BYTES 55296
#define SMEM_BYTES (4096 + 2 * BUF_BYTES)   // 114688 -> 1 CTA/SM

// ============================================================
// Preamble small GEMM: BM=32, BN=32, BK=16, 128 threads,
// software-pipelined (register-staged next-tile LDGs).
// 256 CTAs (~1.7/SM) for latency hiding.
// WRITE_H: also emit fp16 copy of the output.
// ============================================================
template <int ACT, bool WRITE_H>
__device__ __forceinline__ void gemm_small_body(
    const float* __restrict__ A, const float* __restrict__ W,
    const float* __restrict__ bias, float* __restrict__ C,
    __half* __restrict__ Ch, int m0, int n0)
{
    __shared__ float As[16][32];
    __shared__ float Bs[16][32];
    const int t = threadIdx.x;
    const int tx = t & 7, ty = t >> 3;        // 8 x 16 threads
    const int am = t >> 2, akq = (t & 3) * 4; // A: 32 rows x 4 quads
    const int bk = t >> 3, bn = (t & 7) * 4;  // B: 16 rows x 8 quads

    float4 ra, rb;
    auto ldgTiles = [&](int k0) {
        ra = __ldg((const float4*)&A[(size_t)(m0 + am) * DD + k0 + akq]);
        rb = __ldg((const float4*)&W[(size_t)(k0 + bk) * OD + n0 + bn]);
    };

    float acc[2][4] = {};
    ldgTiles(0);

    for (int it = 0; it < 32; it++) {
        if (it) __syncthreads();
        As[akq + 0][am] = ra.x; As[akq + 1][am] = ra.y;
        As[akq + 2][am] = ra.z; As[akq + 3][am] = ra.w;
        *(float4*)&Bs[bk][bn] = rb;
        __syncthreads();
        if (it < 31) ldgTiles((it + 1) * 16);   // prefetch hides behind FMA

        #pragma unroll
        for (int k = 0; k < 16; k++) {
            float a0 = As[k][ty * 2];
            float a1 = As[k][ty * 2 + 1];
            float b[4];
            *(float4*)b = *(const float4*)&Bs[k][tx * 4];
            #pragma unroll
            for (int c = 0; c < 4; c++) {
                acc[0][c] += a0 * b[c];
                acc[1][c] += a1 * b[c];
            }
        }
    }

    #pragma unroll
    for (int r = 0; r < 2; r++) {
        const int m = m0 + ty * 2 + r;
        float4 v; float* vv = (float*)&v;
        #pragma unroll
        for (int c = 0; c < 4; c++) {
            float x = acc[r][c] + __ldg(&bias[n0 + tx * 4 + c]);
            if (ACT == 1) x = fmaxf(x, 0.0f);
            if (ACT == 2) x = 1.0f / (1.0f + __expf(-x));
            vv[c] = x;
        }
        *(float4*)&C[(size_t)m * OD + n0 + tx * 4] = v;
        if (WRITE_H) {
            __half2 p0 = __float22half2_rn(make_float2(v.x, v.y));
            __half2 p1 = __float22half2_rn(make_float2(v.z, v.w));
            *(uint2*)&Ch[(size_t)m * OD + n0 + tx * 4] =
                make_uint2(*(uint32_t*)&p0, *(uint32_t*)&p1);
        }
    }
}

template <int ACT>
__global__ void __launch_bounds__(128)
gemm_small_kernel(const float* __restrict__ A, const float* __restrict__ W,
                  const float* __restrict__ bias, float* __restrict__ C)
{
    gemm_small_body<ACT, false>(A, W, bias, C, nullptr, blockIdx.y * 32, blockIdx.x * 32);
}

// Fused first stage: z=0 -> h = relu(text@Wa1+ba1)
//                    z=1 -> outx = image@Wx+bx (+ fp16 copy outxh)
__global__ void __launch_bounds__(128)
pre_fused_kernel(const float* __restrict__ text, const float* __restrict__ image,
                 const float* __restrict__ Wa1, const float* __restrict__ ba1,
                 const float* __restrict__ Wx,  const float* __restrict__ bx,
                 float* __restrict__ h, float* __restrict__ outx,
                 __half* __restrict__ outxh)
{
    if (blockIdx.z == 0)
        gemm_small_body<1, false>(text, Wa1, ba1, h, nullptr, blockIdx.y * 32, blockIdx.x * 32);
    else
        gemm_small_body<0, true>(image, Wx, bx, outx, outxh, blockIdx.y * 32, blockIdx.x * 32);
}

// ============================================================
// Preamble: row softmax * text
// ============================================================
__global__ void __launch_bounds__(512)
softmax_mul_kernel(const float* __restrict__ logits, const float* __restrict__ text,
                   float* __restrict__ out)
{
    __shared__ float sdata[512];
    const int row = blockIdx.x, t = threadIdx.x;
    const float v = logits[(size_t)row * DD + t];
    sdata[t] = v; __syncthreads();
    for (int s = 256; s > 0; s >>= 1) { if (t < s) sdata[t] = fmaxf(sdata[t], sdata[t + s]); __syncthreads(); }
    const float mx = sdata[0]; __syncthreads();
    const float e = __expf(v - mx);
    sdata[t] = e; __syncthreads();
    for (int s = 256; s > 0; s >>= 1) { if (t < s) sdata[t] += sdata[t + s]; __syncthreads(); }
    out[(size_t)row * DD + t] = e * (1.0f / sdata[0]) * text[(size_t)row * DD + t];
}

// ============================================================
// Preamble: transpose Wo -> fp16:  WoT[o][d] = fp16(Wo[d][o])
// ============================================================
__global__ void __launch_bounds__(256)
transpose_wo_h(const float* __restrict__ Wo, __half* __restrict__ T)
{
    __shared__ float tile[32][33];
    const int bo = blockIdx.x * 32;
    const int bd = blockIdx.y * 32;
    const int x = threadIdx.x, y = threadIdx.y;   // (32, 8)
    #pragma unroll
    for (int r = 0; r < 4; r++)
        tile[y + 8 * r][x] = Wo[(size_t)(bd + y + 8 * r) * OD + bo + x];
    __syncthreads();
    #pragma unroll
    for (int r = 0; r < 4; r++) {
        const int o = bo + y + 8 * r;
        const int d = bd + x;
        T[(size_t)o * DD + d] = __float2half_rn(tile[x][y + 8 * r]);
    }
}

__global__ void mul_kernel(const float* __restrict__ a, const float* __restrict__ b,
                           float* __restrict__ c, int n)
{
    int idx = blockIdx.x * blockDim.x + threadIdx.x;
    if (idx < n) c[idx] = a[idx] * b[idx];
}

// ============================================================
// Big einsum via single-pass fp16 HMMA, 2 i-values per CTA
// (R10/R11 best structure, unchanged):
//   out[i,j,o] = sum_d gate[i,d]*outx[j,d]*Wo[d,o] + bo[o]
// grid (4 o-tiles, 4 j-tiles, 256 i-pairs), 256 threads (8 warps).
// ============================================================
__global__ void __launch_bounds__(256, 1)
big_einsum_hmma_kernel(const __half* __restrict__ outxh, const float* __restrict__ gate,
                       const float* __restrict__ bo, float* __restrict__ out)
{
    extern __shared__ char dynsmem[];
    float* gs = (float*)dynsmem;   // [0..511]=gate(i0), [512..1023]=gate(i1)
    const uint32_t sbase = smem_u32(dynsmem) + 4096u;

    const int i0 = blockIdx.z * 2;
    const int j0 = blockIdx.y * 128;
    const int o0 = blockIdx.x * 128;
    const int tid  = threadIdx.x;
    const int wid  = tid >> 5;
    const int lane = tid & 31;
    const int warp_m = wid & 3;     // 4 x 32 rows (j)
    const int warp_n = wid >> 2;    // 2 x 64 cols (o)

    gs[tid]        = gate[(size_t)i0 * DD + tid];
    gs[tid + 256]  = gate[(size_t)i0 * DD + tid + 256];
    gs[tid + 512]  = gate[(size_t)(i0 + 1) * DD + tid];
    gs[tid + 768]  = gate[(size_t)(i0 + 1) * DD + tid + 256];

    const int arow = tid >> 1;
    const int ach  = (tid & 1) * 32;

    auto cpB = [&](int c, int buf) {
        const int c0 = c * 64;
        const uint32_t bdst = sbase + buf * BUF_BYTES + OFF_B;
        #pragma unroll
        for (int q = 0; q < 4; q++) {
            const int g   = tid + q * 256;
            const int row = g >> 3;
            const int ck  = g & 7;
            const uint32_t dso = (uint32_t)(row * ASTRIDE + ck * 16);
            const __half* src = g_WoT + (size_t)(o0 + row) * DD + c0 + ck * 8;
            CP_ASYNC_16(bdst + dso, src);
        }
        CP_ASYNC_COMMIT();
    };

    uint4 av[4];
    auto loadA = [&](int c) {
        const __half* p = outxh + (size_t)(j0 + arow) * DD + c * 64 + ach;
        #pragma unroll
        for (int q = 0; q < 4; q++) av[q] = __ldg((const uint4*)(p + q * 8));
    };

    auto storeA = [&](int c, int buf) {
        const int d0 = c * 64 + ach;
        #pragma unroll
        for (int iv = 0; iv < 2; iv++) {
            const uint32_t ad = sbase + buf * BUF_BYTES
                              + (iv ? OFF_A1 : OFF_A0) + arow * ASTRIDE + ach * 2;
            const float* gp = gs + iv * 512 + d0;
            #pragma unroll
            for (int h = 0; h < 4; h++) {
                const __half2* xa = (const __half2*)&av[h];
                uint32_t w[4];
                #pragma unroll
                for (int q = 0; q < 4; q++) {
                    float2 xf = __half22float2(xa[q]);
                    const float2 gf = *(const float2*)&gp[h * 8 + q * 2];
                    __half2 r = __float22half2_rn(make_float2(xf.x * gf.x, xf.y * gf.y));
                    w[q] = *(uint32_t*)&r;
                }
                asm volatile("st.shared.v4.b32 [%0], {%1,%2,%3,%4};"
                             :: "r"(ad + h * 16), "r"(w[0]), "r"(w[1]), "r"(w[2]), "r"(w[3]));
            }
        }
    };

    const uint32_t a_lane = (uint32_t)(((lane & 7) + ((lane >> 3) & 1) * 8) * ASTRIDE
                                       + (lane >> 4) * 16);
    const uint32_t b_lane = (uint32_t)(((lane & 7) + (lane >> 4) * 8) * ASTRIDE
                                       + ((lane >> 3) & 1) * 16);
    const uint32_t a_warp = (uint32_t)(warp_m * 32 * ASTRIDE);
    const uint32_t b_warp = (uint32_t)(warp_n * 64 * ASTRIDE);

    float acc0[2][8][4] = {};
    float acc1[2][8][4] = {};

    loadA(0);
    cpB(0, 0);
    __syncthreads();
    storeA(0, 0);
    CP_ASYNC_WAIT0();
    __syncthreads();

    for (int c = 0; c < 8; c++) {
        const int buf = c & 1;
        if (c < 7) { loadA(c + 1); cpB(c + 1, buf ^ 1); }

        const uint32_t bb = sbase + buf * BUF_BYTES;
        #pragma unroll
        for (int ks = 0; ks < 4; ks++) {
            uint32_t a0[2][4], a1[2][4];
            #pragma unroll
            for (int mt = 0; mt < 2; mt++) {
                ldsm_x4(a0[mt], bb + OFF_A0 + a_warp + a_lane + mt * 16 * ASTRIDE + ks * 32);
                ldsm_x4(a1[mt], bb + OFF_A1 + a_warp + a_lane + mt * 16 * ASTRIDE + ks * 32);
            }
            #pragma unroll
            for (int g = 0; g < 4; g++) {
                uint32_t bh[4];
                ldsm_x4(bh, bb + OFF_B + b_warp + b_lane + g * 16 * ASTRIDE + ks * 32);
                #pragma unroll
                for (int mt = 0; mt < 2; mt++) {
                    mma_fp16(acc0[mt][g * 2],     a0[mt], bh[0], bh[1]);
                    mma_fp16(acc0[mt][g * 2 + 1], a0[mt], bh[2], bh[3]);
                    mma_fp16(acc1[mt][g * 2],     a1[mt], bh[0], bh[1]);
                    mma_fp16(acc1[mt][g * 2 + 1], a1[mt], bh[2], bh[3]);
                }
            }
        }

        if (c < 7) {
            storeA(c + 1, buf ^ 1);
            CP_ASYNC_WAIT0();
            __syncthreads();
        }
    }

    const int colb = o0 + warp_n * 64 + (lane & 3) * 2;
    float2 bv[8];
    #pragma unroll
    for (int nj = 0; nj < 8; nj++)
        bv[nj] = __ldg((const float2*)&bo[colb + nj * 8]);

    const int rowb = j0 + warp_m * 32 + (lane >> 2);
    #pragma unroll
    for (int iv = 0; iv < 2; iv++) {
        #pragma unroll
        for (int mt = 0; mt < 2; mt++) {
            #pragma unroll
            for (int h = 0; h < 2; h++) {
                const size_t rbase = ((size_t)(i0 + iv) * NB + (rowb + mt * 16 + h * 8)) * OD;
                #pragma unroll
                for (int nj = 0; nj < 8; nj++) {
                    const float* a = iv ? acc1[mt][nj] : acc0[mt][nj];
                    float2 v;
                    v.x = a[h * 2]     + bv[nj].x;
                    v.y = a[h * 2 + 1] + bv[nj].y;
                    *(float2*)&out[rbase + colb + nj * 8] = v;
                }
            }
        }
    }
}

// ============================================================
// kernel_launch
// ============================================================
extern "C" void kernel_launch(void* const* d_in, const int* in_sizes, int n_in,
                              void* d_out, int out_size)
{
    const float* image = (const float*)d_in[0];
    const float* text  = (const float*)d_in[1];
    const float* Wx  = (const float*)d_in[3];
    const float* bx  = (const float*)d_in[4];
    const float* Wy  = (const float*)d_in[5];
    const float* by  = (const float*)d_in[6];
    const float* Wo  = (const float*)d_in[7];
    const float* bo  = (const float*)d_in[8];
    const float* Wa1 = (const float*)d_in[9];
    const float* ba1 = (const float*)d_in[10];
    const float* Wa2 = (const float*)d_in[11];
    const float* ba2 = (const float*)d_in[12];
    float* out = (float*)d_out;

    float *h, *logits, *textw, *outx, *gate, *tmp;
    __half *wot, *outxh;
    cudaGetSymbolAddress((void**)&h,      g_h);
    cudaGetSymbolAddress((void**)&logits, g_logits);
    cudaGetSymbolAddress((void**)&textw,  g_textw);
    cudaGetSymbolAddress((void**)&outx,   g_outx);
    cudaGetSymbolAddress((void**)&gate,   g_gate);
    cudaGetSymbolAddress((void**)&tmp,    g_tmp);
    cudaGetSymbolAddress((void**)&wot,    g_WoT);
    cudaGetSymbolAddress((void**)&outxh,  g_outxh);

    cudaFuncSetAttribute(big_einsum_hmma_kernel,
                         cudaFuncAttributeMaxDynamicSharedMemorySize, SMEM_BYTES);

    const dim3 gsm(OD / 32, NB / 32);   // (16, 16) = 256 CTAs

    // Wo transpose -> fp16
    transpose_wo_h<<<dim3(16, 16), dim3(32, 8)>>>(Wo, wot);
    // Stage 1 fused: h = relu(text@Wa1+ba1)  and  outx = image@Wx+bx (+ outxh fp16)
    pre_fused_kernel<<<dim3(OD / 32, NB / 32, 2), 128>>>(text, image, Wa1, ba1, Wx, bx,
                                                         h, outx, outxh);
    // logits = h@Wa2+ba2
    gemm_small_kernel<0><<<gsm, 128>>>(h, Wa2, ba2, logits);
    // textw = softmax(logits) * text
    softmax_mul_kernel<<<NB, 512>>>(logits, text, textw);
    // gate = sigmoid(textw@Wy+by)
    gemm_small_kernel<2><<<gsm, 128>>>(textw, Wy, by, gate);

    if (out_size == NB * NB * OD) {
        dim3 grid(OD / 128, NB / 128, NB / 2);   // (4, 4, 256)
        big_einsum_hmma_kernel<<<grid, 256, SMEM_BYTES>>>(outxh, gate, bo, out);
    } else {
        mul_kernel<<<(NB * DD + 255) / 256, 256>>>(gate, outx, tmp, NB * DD);
        gemm_small_kernel<0><<<gsm, 128>>>(tmp, Wo, bo, out);
    }
}

// round 14
// speedup vs baseline: 1.3179x; 1.0158x over previous
#include <cuda_runtime.h>
#include <cuda_fp16.h>
#include <cstdint>

#define NB 512   // batch
#define DD 512   // embed dim
#define OD 512   // out dim

// -------- scratch (no cudaMalloc allowed) --------
__device__ float g_h[NB * DD];
__device__ float g_logits[NB * DD];
__device__ float g_textw[NB * DD];
__device__ float g_outx[NB * DD];
__device__ float g_gate[NB * DD];
__device__ float g_tmp[NB * DD];
__device__ __half g_outxh[NB * DD];  // fp16 copy of outx
__device__ __half g_WoT[OD * DD];    // WoT[o][d] = fp16(Wo[d][o])

// ============================================================
// Helpers (plain sm_80+ PTX: mma.sync / ldmatrix / cp.async)
// ============================================================
__device__ __forceinline__ uint32_t smem_u32(const void* p) {
    uint32_t a;
    asm("{ .reg .u64 t; cvta.to.shared.u64 t, %1; cvt.u32.u64 %0, t; }"
        : "=r"(a) : "l"(p));
    return a;
}

#define CP_ASYNC_16(dst, src) \
    asm volatile("cp.async.cg.shared.global [%0], [%1], 16;" \
                 :: "r"((uint32_t)(dst)), "l"(src))
#define CP_ASYNC_COMMIT() asm volatile("cp.async.commit_group;" ::: "memory")
#define CP_ASYNC_WAIT0()  asm volatile("cp.async.wait_group 0;" ::: "memory")

__device__ __forceinline__ void ldsm_x4(uint32_t r[4], uint32_t addr) {
    asm volatile("ldmatrix.sync.aligned.m8n8.x4.shared.b16 {%0,%1,%2,%3}, [%4];"
                 : "=r"(r[0]), "=r"(r[1]), "=r"(r[2]), "=r"(r[3]) : "r"(addr));
}

__device__ __forceinline__ void mma_fp16(float c[4], const uint32_t a[4],
                                         const uint32_t b0, const uint32_t b1) {
    asm volatile(
        "mma.sync.aligned.m16n8k16.row.col.f32.f16.f16.f32 "
        "{%0,%1,%2,%3}, {%4,%5,%6,%7}, {%8,%9}, {%0,%1,%2,%3};"
        : "+f"(c[0]), "+f"(c[1]), "+f"(c[2]), "+f"(c[3])
        : "r"(a[0]), "r"(a[1]), "r"(a[2]), "r"(a[3]), "r"(b0), "r"(b1));
}

// ============================================================
// smem layout for big kernel (dynamic) — R10 structure
//   gate rows (fp32, 2 i): 4096 B
//   K-chunk = 64: rows hold 64 fp16 = 128B data + 16B pad -> stride 144
//   2 buffers, each: A0(18432) A1(18432) B(128x144=18432) = 55296 B
// ============================================================
#define ASTRIDE 144
#define OFF_A0 0
#define OFF_A1 18432
#define OFF_B  36864
#define BUF_BYTES 55296
#define SMEM_BYTES (4096 + 2 * BUF_BYTES)   // 114688 -> 1 CTA/SM

// ============================================================
// Preamble small GEMM (R11 best): BM=64, BN=32, BK=16, 128 thr,
// software-pipelined register-staged LDGs.
// ============================================================
template <int ACT, bool WRITE_H>
__device__ __forceinline__ void gemm_small_body(
    const float* __restrict__ A, const float* __restrict__ W,
    const float* __restrict__ bias, float* __restrict__ C,
    __half* __restrict__ Ch, int m0, int n0)
{
    __shared__ float As[16][64];
    __shared__ float Bs[16][32];
    const int t = threadIdx.x;
    const int tx = t & 7, ty = t >> 3;
    const int am = t >> 1, akq = (t & 1) * 8;
    const int bk = t >> 3, bn = (t & 7) * 4;

    float4 ra0, ra1, rb;
    auto ldgTiles = [&](int k0) {
        ra0 = __ldg((const float4*)&A[(size_t)(m0 + am) * DD + k0 + akq]);
        ra1 = __ldg((const float4*)&A[(size_t)(m0 + am) * DD + k0 + akq + 4]);
        rb  = __ldg((const float4*)&W[(size_t)(k0 + bk) * OD + n0 + bn]);
    };

    float acc[4][4] = {};
    ldgTiles(0);

    for (int it = 0; it < 32; it++) {
        if (it) __syncthreads();
        As[akq + 0][am] = ra0.x; As[akq + 1][am] = ra0.y;
        As[akq + 2][am] = ra0.z; As[akq + 3][am] = ra0.w;
        As[akq + 4][am] = ra1.x; As[akq + 5][am] = ra1.y;
        As[akq + 6][am] = ra1.z; As[akq + 7][am] = ra1.w;
        *(float4*)&Bs[bk][bn] = rb;
        __syncthreads();
        if (it < 31) ldgTiles((it + 1) * 16);

        #pragma unroll
        for (int k = 0; k < 16; k++) {
            float a[4], b[4];
            *(float4*)a = *(const float4*)&As[k][ty * 4];
            *(float4*)b = *(const float4*)&Bs[k][tx * 4];
            #pragma unroll
            for (int r = 0; r < 4; r++)
                #pragma unroll
                for (int c = 0; c < 4; c++)
                    acc[r][c] += a[r] * b[c];
        }
    }

    #pragma unroll
    for (int r = 0; r < 4; r++) {
        const int m = m0 + ty * 4 + r;
        float4 v; float* vv = (float*)&v;
        #pragma unroll
        for (int c = 0; c < 4; c++) {
            float x = acc[r][c] + __ldg(&bias[n0 + tx * 4 + c]);
            if (ACT == 1) x = fmaxf(x, 0.0f);
            if (ACT == 2) x = 1.0f / (1.0f + __expf(-x));
            vv[c] = x;
        }
        *(float4*)&C[(size_t)m * OD + n0 + tx * 4] = v;
        if (WRITE_H) {
            __half2 p0 = __float22half2_rn(make_float2(v.x, v.y));
            __half2 p1 = __float22half2_rn(make_float2(v.z, v.w));
            *(uint2*)&Ch[(size_t)m * OD + n0 + tx * 4] =
                make_uint2(*(uint32_t*)&p0, *(uint32_t*)&p1);
        }
    }
}

template <int ACT>
__global__ void __launch_bounds__(128)
gemm_small_kernel(const float* __restrict__ A, const float* __restrict__ W,
                  const float* __restrict__ bias, float* __restrict__ C)
{
    gemm_small_body<ACT, false>(A, W, bias, C, nullptr, blockIdx.y * 64, blockIdx.x * 32);
}

__global__ void __launch_bounds__(128)
pre_fused_kernel(const float* __restrict__ text, const float* __restrict__ image,
                 const float* __restrict__ Wa1, const float* __restrict__ ba1,
                 const float* __restrict__ Wx,  const float* __restrict__ bx,
                 float* __restrict__ h, float* __restrict__ outx,
                 __half* __restrict__ outxh)
{
    if (blockIdx.z == 0)
        gemm_small_body<1, false>(text, Wa1, ba1, h, nullptr, blockIdx.y * 64, blockIdx.x * 32);
    else
        gemm_small_body<0, true>(image, Wx, bx, outx, outxh, blockIdx.y * 64, blockIdx.x * 32);
}

// ============================================================
// Preamble: row softmax * text
// ============================================================
__global__ void __launch_bounds__(512)
softmax_mul_kernel(const float* __restrict__ logits, const float* __restrict__ text,
                   float* __restrict__ out)
{
    __shared__ float sdata[512];
    const int row = blockIdx.x, t = threadIdx.x;
    const float v = logits[(size_t)row * DD + t];
    sdata[t] = v; __syncthreads();
    for (int s = 256; s > 0; s >>= 1) { if (t < s) sdata[t] = fmaxf(sdata[t], sdata[t + s]); __syncthreads(); }
    const float mx = sdata[0]; __syncthreads();
    const float e = __expf(v - mx);
    sdata[t] = e; __syncthreads();
    for (int s = 256; s > 0; s >>= 1) { if (t < s) sdata[t] += sdata[t + s]; __syncthreads(); }
    out[(size_t)row * DD + t] = e * (1.0f / sdata[0]) * text[(size_t)row * DD + t];
}

// ============================================================
// Preamble: transpose Wo -> fp16
// ============================================================
__global__ void __launch_bounds__(256)
transpose_wo_h(const float* __restrict__ Wo, __half* __restrict__ T)
{
    __shared__ float tile[32][33];
    const int bo = blockIdx.x * 32;
    const int bd = blockIdx.y * 32;
    const int x = threadIdx.x, y = threadIdx.y;
    #pragma unroll
    for (int r = 0; r < 4; r++)
        tile[y + 8 * r][x] = Wo[(size_t)(bd + y + 8 * r) * OD + bo + x];
    __syncthreads();
    #pragma unroll
    for (int r = 0; r < 4; r++) {
        const int o = bo + y + 8 * r;
        const int d = bd + x;
        T[(size_t)o * DD + d] = __float2half_rn(tile[x][y + 8 * r]);
    }
}

__global__ void mul_kernel(const float* __restrict__ a, const float* __restrict__ b,
                           float* __restrict__ c, int n)
{
    int idx = blockIdx.x * blockDim.x + threadIdx.x;
    if (idx < n) c[idx] = a[idx] * b[idx];
}

// ============================================================
// Big einsum, fp16 HMMA, 2 i/CTA (R10 structure) with
// REGISTER-PIPELINED fragment loads: next B frag / next ks A
// frags are ldsm'd BEFORE the current MMAs consume theirs,
// hiding the ~30cyc LDS latency edge per g-iteration.
// grid (4 o, 4 j, 256 i-pairs), 256 threads (8 warps).
// ============================================================
__global__ void __launch_bounds__(256, 1)
big_einsum_hmma_kernel(const __half* __restrict__ outxh, const float* __restrict__ gate,
                       const float* __restrict__ bo, float* __restrict__ out)
{
    extern __shared__ char dynsmem[];
    float* gs = (float*)dynsmem;   // [0..511]=gate(i0), [512..1023]=gate(i1)
    const uint32_t sbase = smem_u32(dynsmem) + 4096u;

    const int i0 = blockIdx.z * 2;
    const int j0 = blockIdx.y * 128;
    const int o0 = blockIdx.x * 128;
    const int tid  = threadIdx.x;
    const int wid  = tid >> 5;
    const int lane = tid & 31;
    const int warp_m = wid & 3;     // 4 x 32 rows (j)
    const int warp_n = wid >> 2;    // 2 x 64 cols (o)

    gs[tid]        = gate[(size_t)i0 * DD + tid];
    gs[tid + 256]  = gate[(size_t)i0 * DD + tid + 256];
    gs[tid + 512]  = gate[(size_t)(i0 + 1) * DD + tid];
    gs[tid + 768]  = gate[(size_t)(i0 + 1) * DD + tid + 256];

    const int arow = tid >> 1;
    const int ach  = (tid & 1) * 32;

    auto cpB = [&](int c, int buf) {
        const int c0 = c * 64;
        const uint32_t bdst = sbase + buf * BUF_BYTES + OFF_B;
        #pragma unroll
        for (int q = 0; q < 4; q++) {
            const int g   = tid + q * 256;
            const int row = g >> 3;
            const int ck  = g & 7;
            const uint32_t dso = (uint32_t)(row * ASTRIDE + ck * 16);
            const __half* src = g_WoT + (size_t)(o0 + row) * DD + c0 + ck * 8;
            CP_ASYNC_16(bdst + dso, src);
        }
        CP_ASYNC_COMMIT();
    };

    uint4 av[4];
    auto loadA = [&](int c) {
        const __half* p = outxh + (size_t)(j0 + arow) * DD + c * 64 + ach;
        #pragma unroll
        for (int q = 0; q < 4; q++) av[q] = __ldg((const uint4*)(p + q * 8));
    };

    auto storeA = [&](int c, int buf) {
        const int d0 = c * 64 + ach;
        #pragma unroll
        for (int iv = 0; iv < 2; iv++) {
            const uint32_t ad = sbase + buf * BUF_BYTES
                              + (iv ? OFF_A1 : OFF_A0) + arow * ASTRIDE + ach * 2;
            const float* gp = gs + iv * 512 + d0;
            #pragma unroll
            for (int h = 0; h < 4; h++) {
                const __half2* xa = (const __half2*)&av[h];
                uint32_t w[4];
                #pragma unroll
                for (int q = 0; q < 4; q++) {
                    float2 xf = __half22float2(xa[q]);
                    const float2 gf = *(const float2*)&gp[h * 8 + q * 2];
                    __half2 r = __float22half2_rn(make_float2(xf.x * gf.x, xf.y * gf.y));
                    w[q] = *(uint32_t*)&r;
                }
                asm volatile("st.shared.v4.b32 [%0], {%1,%2,%3,%4};"
                             :: "r"(ad + h * 16), "r"(w[0]), "r"(w[1]), "r"(w[2]), "r"(w[3]));
            }
        }
    };

    const uint32_t a_lane = (uint32_t)(((lane & 7) + ((lane >> 3) & 1) * 8) * ASTRIDE
                                       + (lane >> 4) * 16);
    const uint32_t b_lane = (uint32_t)(((lane & 7) + (lane >> 4) * 8) * ASTRIDE
                                       + ((lane >> 3) & 1) * 16);
    const uint32_t a_warp = (uint32_t)(warp_m * 32 * ASTRIDE);
    const uint32_t b_warp = (uint32_t)(warp_n * 64 * ASTRIDE);

    float acc0[2][8][4] = {};
    float acc1[2][8][4] = {};

    loadA(0);
    cpB(0, 0);
    __syncthreads();
    storeA(0, 0);
    CP_ASYNC_WAIT0();
    __syncthreads();

    for (int c = 0; c < 8; c++) {
        const int buf = c & 1;
        if (c < 7) { loadA(c + 1); cpB(c + 1, buf ^ 1); }

        const uint32_t bb = sbase + buf * BUF_BYTES;

        // ---- register-pipelined fragment stream ----
        uint32_t a0c[2][4], a1c[2][4], bhc[4];
        #pragma unroll
        for (int mt = 0; mt < 2; mt++) {
            ldsm_x4(a0c[mt], bb + OFF_A0 + a_warp + a_lane + mt * 16 * ASTRIDE);
            ldsm_x4(a1c[mt], bb + OFF_A1 + a_warp + a_lane + mt * 16 * ASTRIDE);
        }
        ldsm_x4(bhc, bb + OFF_B + b_warp + b_lane);

        #pragma unroll
        for (int ks = 0; ks < 4; ks++) {
            uint32_t a0n[2][4], a1n[2][4];
            #pragma unroll
            for (int g = 0; g < 4; g++) {
                uint32_t bhn[4];
                // prefetch next fragments BEFORE consuming current ones
                if (g < 3) {
                    ldsm_x4(bhn, bb + OFF_B + b_warp + b_lane
                                  + (g + 1) * 16 * ASTRIDE + ks * 32);
                } else if (ks < 3) {
                    #pragma unroll
                    for (int mt = 0; mt < 2; mt++) {
                        ldsm_x4(a0n[mt], bb + OFF_A0 + a_warp + a_lane
                                          + mt * 16 * ASTRIDE + (ks + 1) * 32);
                        ldsm_x4(a1n[mt], bb + OFF_A1 + a_warp + a_lane
                                          + mt * 16 * ASTRIDE + (ks + 1) * 32);
                    }
                    ldsm_x4(bhn, bb + OFF_B + b_warp + b_lane + (ks + 1) * 32);
                }
                // consume current fragments
                #pragma unroll
                for (int mt = 0; mt < 2; mt++) {
                    mma_fp16(acc0[mt][g * 2],     a0c[mt], bhc[0], bhc[1]);
                    mma_fp16(acc0[mt][g * 2 + 1], a0c[mt], bhc[2], bhc[3]);
                    mma_fp16(acc1[mt][g * 2],     a1c[mt], bhc[0], bhc[1]);
                    mma_fp16(acc1[mt][g * 2 + 1], a1c[mt], bhc[2], bhc[3]);
                }
                // rotate B
                if (g < 3 || ks < 3) {
                    #pragma unroll
                    for (int q = 0; q < 4; q++) bhc[q] = bhn[q];
                }
            }
            // rotate A
            if (ks < 3) {
                #pragma unroll
                for (int mt = 0; mt < 2; mt++)
                    #pragma unroll
                    for (int q = 0; q < 4; q++) {
                        a0c[mt][q] = a0n[mt][q];
                        a1c[mt][q] = a1n[mt][q];
                    }
            }
        }

        if (c < 7) {
            storeA(c + 1, buf ^ 1);
            CP_ASYNC_WAIT0();
            __syncthreads();
        }
    }

    const int colb = o0 + warp_n * 64 + (lane & 3) * 2;
    float2 bv[8];
    #pragma unroll
    for (int nj = 0; nj < 8; nj++)
        bv[nj] = __ldg((const float2*)&bo[colb + nj * 8]);

    const int rowb = j0 + warp_m * 32 + (lane >> 2);
    #pragma unroll
    for (int iv = 0; iv < 2; iv++) {
        #pragma unroll
        for (int mt = 0; mt < 2; mt++) {
            #pragma unroll
            for (int h = 0; h < 2; h++) {
                const size_t rbase = ((size_t)(i0 + iv) * NB + (rowb + mt * 16 + h * 8)) * OD;
                #pragma unroll
                for (int nj = 0; nj < 8; nj++) {
                    const float* a = iv ? acc1[mt][nj] : acc0[mt][nj];
                    float2 v;
                    v.x = a[h * 2]     + bv[nj].x;
                    v.y = a[h * 2 + 1] + bv[nj].y;
                    *(float2*)&out[rbase + colb + nj * 8] = v;
                }
            }
        }
    }
}

// ============================================================
// kernel_launch
// ============================================================
extern "C" void kernel_launch(void* const* d_in, const int* in_sizes, int n_in,
                              void* d_out, int out_size)
{
    const float* image = (const float*)d_in[0];
    const float* text  = (const float*)d_in[1];
    const float* Wx  = (const float*)d_in[3];
    const float* bx  = (const float*)d_in[4];
    const float* Wy  = (const float*)d_in[5];
    const float* by  = (const float*)d_in[6];
    const float* Wo  = (const float*)d_in[7];
    const float* bo  = (const float*)d_in[8];
    const float* Wa1 = (const float*)d_in[9];
    const float* ba1 = (const float*)d_in[10];
    const float* Wa2 = (const float*)d_in[11];
    const float* ba2 = (const float*)d_in[12];
    float* out = (float*)d_out;

    float *h, *logits, *textw, *outx, *gate, *tmp;
    __half *wot, *outxh;
    cudaGetSymbolAddress((void**)&h,      g_h);
    cudaGetSymbolAddress((void**)&logits, g_logits);
    cudaGetSymbolAddress((void**)&textw,  g_textw);
    cudaGetSymbolAddress((void**)&outx,   g_outx);
    cudaGetSymbolAddress((void**)&gate,   g_gate);
    cudaGetSymbolAddress((void**)&tmp,    g_tmp);
    cudaGetSymbolAddress((void**)&wot,    g_WoT);
    cudaGetSymbolAddress((void**)&outxh,  g_outxh);

    cudaFuncSetAttribute(big_einsum_hmma_kernel,
                         cudaFuncAttributeMaxDynamicSharedMemorySize, SMEM_BYTES);

    const dim3 gsm(OD / 32, NB / 64);   // (16, 8) = 128 CTAs

    // Wo transpose -> fp16
    transpose_wo_h<<<dim3(16, 16), dim3(32, 8)>>>(Wo, wot);
    // Stage 1 fused: h = relu(text@Wa1+ba1)  and  outx = image@Wx+bx (+ outxh fp16)
    pre_fused_kernel<<<dim3(OD / 32, NB / 64, 2), 128>>>(text, image, Wa1, ba1, Wx, bx,
                                                         h, outx, outxh);
    // logits = h@Wa2+ba2
    gemm_small_kernel<0><<<gsm, 128>>>(h, Wa2, ba2, logits);
    // textw = softmax(logits) * text
    softmax_mul_kernel<<<NB, 512>>>(logits, text, textw);
    // gate = sigmoid(textw@Wy+by)
    gemm_small_kernel<2><<<gsm, 128>>>(textw, Wy, by, gate);

    if (out_size == NB * NB * OD) {
        dim3 grid(OD / 128, NB / 128, NB / 2);   // (4, 4, 256)
        big_einsum_hmma_kernel<<<grid, 256, SMEM_BYTES>>>(outxh, gate, bo, out);
    } else {
        mul_kernel<<<(NB * DD + 255) / 256, 256>>>(gate, outx, tmp, NB * DD);
        gemm_small_kernel<0><<<gsm, 128>>>(tmp, Wo, bo, out);
    }
}

// round 15
// speedup vs baseline: 1.3497x; 1.0241x over previous
#include <cuda_runtime.h>
#include <cuda_fp16.h>
#include <cstdint>

#define NB 512   // batch
#define DD 512   // embed dim
#define OD 512   // out dim

// -------- scratch (no cudaMalloc allowed) --------
__device__ float g_h[NB * DD];
__device__ float g_logits[NB * DD];
__device__ float g_textw[NB * DD];
__device__ float g_outx[NB * DD];
__device__ float g_gate[NB * DD];
__device__ float g_tmp[NB * DD];
__device__ __half g_outxh[NB * DD];  // fp16 copy of outx
__device__ __half g_WoT[OD * DD];    // WoT[o][d] = fp16(Wo[d][o])

// ============================================================
// Helpers (plain sm_80+ PTX: mma.sync / ldmatrix / cp.async)
// ============================================================
__device__ __forceinline__ uint32_t smem_u32(const void* p) {
    uint32_t a;
    asm("{ .reg .u64 t; cvta.to.shared.u64 t, %1; cvt.u32.u64 %0, t; }"
        : "=r"(a) : "l"(p));
    return a;
}

#define CP_ASYNC_16(dst, src) \
    asm volatile("cp.async.cg.shared.global [%0], [%1], 16;" \
                 :: "r"((uint32_t)(dst)), "l"(src))
#define CP_ASYNC_COMMIT() asm volatile("cp.async.commit_group;" ::: "memory")
#define CP_ASYNC_WAIT0()  asm volatile("cp.async.wait_group 0;" ::: "memory")

__device__ __forceinline__ void ldsm_x4(uint32_t r[4], uint32_t addr) {
    asm volatile("ldmatrix.sync.aligned.m8n8.x4.shared.b16 {%0,%1,%2,%3}, [%4];"
                 : "=r"(r[0]), "=r"(r[1]), "=r"(r[2]), "=r"(r[3]) : "r"(addr));
}

__device__ __forceinline__ void mma_fp16(float c[4], const uint32_t a[4],
                                         const uint32_t b0, const uint32_t b1) {
    asm volatile(
        "mma.sync.aligned.m16n8k16.row.col.f32.f16.f16.f32 "
        "{%0,%1,%2,%3}, {%4,%5,%6,%7}, {%8,%9}, {%0,%1,%2,%3};"
        : "+f"(c[0]), "+f"(c[1]), "+f"(c[2]), "+f"(c[3])
        : "r"(a[0]), "r"(a[1]), "r"(a[2]), "r"(a[3]), "r"(b0), "r"(b1));
}

// ============================================================
// smem layout for big kernel (dynamic) — R10/R14 structure
//   gate rows (fp32, 2 i): 4096 B
//   K-chunk = 64: rows hold 64 fp16 = 128B data + 16B pad -> stride 144
//   2 buffers, each: A0(18432) A1(18432) B(128x144=18432) = 55296 B
// ============================================================
#define ASTRIDE 144
#define OFF_A0 0
#define OFF_A1 18432
#define OFF_B  36864
#define BUF_BYTES 55296
#define SMEM_BYTES (4096 + 2 * BUF_BYTES)   // 114688 -> 1 CTA/SM

// ============================================================
// Preamble small GEMM: BM=64, BN=32, BK=32, 128 threads,
// software-pipelined register-staged LDGs (half the barriers of BK=16).
// Per-thread k-order unchanged -> bit-identical to BK=16 version.
// ============================================================
template <int ACT, bool WRITE_H>
__device__ __forceinline__ void gemm_small_body(
    const float* __restrict__ A, const float* __restrict__ W,
    const float* __restrict__ bias, float* __restrict__ C,
    __half* __restrict__ Ch, int m0, int n0)
{
    __shared__ float As[32][64];   // [k][m] 8KB
    __shared__ float Bs[32][36];   // [k][n] padded stride 36 (bank-safe)
    const int t = threadIdx.x;
    const int tx = t & 7, ty = t >> 3;
    const int am = t >> 1, akq = (t & 1) * 16;  // A: row am, 16 cols
    const int bk = t >> 2, bn = (t & 3) * 8;    // B: row bk, 8 cols

    float4 ra[4], rb[2];
    auto ldgTiles = [&](int k0) {
        #pragma unroll
        for (int q = 0; q < 4; q++)
            ra[q] = __ldg((const float4*)&A[(size_t)(m0 + am) * DD + k0 + akq + q * 4]);
        #pragma unroll
        for (int q = 0; q < 2; q++)
            rb[q] = __ldg((const float4*)&W[(size_t)(k0 + bk) * OD + n0 + bn + q * 4]);
    };

    float acc[4][4] = {};
    ldgTiles(0);

    for (int it = 0; it < 16; it++) {
        if (it) __syncthreads();               // consumers of prev tile done
        #pragma unroll
        for (int q = 0; q < 4; q++) {
            As[akq + q * 4 + 0][am] = ra[q].x;
            As[akq + q * 4 + 1][am] = ra[q].y;
            As[akq + q * 4 + 2][am] = ra[q].z;
            As[akq + q * 4 + 3][am] = ra[q].w;
        }
        *(float4*)&Bs[bk][bn]     = rb[0];
        *(float4*)&Bs[bk][bn + 4] = rb[1];
        __syncthreads();                       // tile visible
        if (it < 15) ldgTiles((it + 1) * 32);  // prefetch hides behind FMA

        #pragma unroll
        for (int k = 0; k < 32; k++) {
            float a[4], b[4];
            *(float4*)a = *(const float4*)&As[k][ty * 4];
            *(float4*)b = *(const float4*)&Bs[k][tx * 4];
            #pragma unroll
            for (int r = 0; r < 4; r++)
                #pragma unroll
                for (int c = 0; c < 4; c++)
                    acc[r][c] += a[r] * b[c];
        }
    }

    #pragma unroll
    for (int r = 0; r < 4; r++) {
        const int m = m0 + ty * 4 + r;
        float4 v; float* vv = (float*)&v;
        #pragma unroll
        for (int c = 0; c < 4; c++) {
            float x = acc[r][c] + __ldg(&bias[n0 + tx * 4 + c]);
            if (ACT == 1) x = fmaxf(x, 0.0f);
            if (ACT == 2) x = 1.0f / (1.0f + __expf(-x));
            vv[c] = x;
        }
        *(float4*)&C[(size_t)m * OD + n0 + tx * 4] = v;
        if (WRITE_H) {
            __half2 p0 = __float22half2_rn(make_float2(v.x, v.y));
            __half2 p1 = __float22half2_rn(make_float2(v.z, v.w));
            *(uint2*)&Ch[(size_t)m * OD + n0 + tx * 4] =
                make_uint2(*(uint32_t*)&p0, *(uint32_t*)&p1);
        }
    }
}

template <int ACT>
__global__ void __launch_bounds__(128)
gemm_small_kernel(const float* __restrict__ A, const float* __restrict__ W,
                  const float* __restrict__ bias, float* __restrict__ C)
{
    gemm_small_body<ACT, false>(A, W, bias, C, nullptr, blockIdx.y * 64, blockIdx.x * 32);
}

// ---- 128-thread Wo-transpose body: region 32(o) x 64(d) per block ----
__device__ __forceinline__ void transpose_wo_body(
    const float* __restrict__ Wo, __half* __restrict__ T, int bo, int bd)
{
    __shared__ float tile[32][33];
    const int x = threadIdx.x & 31;   // 32
    const int y = threadIdx.x >> 5;   // 4
    #pragma unroll
    for (int sub = 0; sub < 2; sub++) {
        const int bds = bd + sub * 32;
        #pragma unroll
        for (int r = 0; r < 8; r++)
            tile[y + 4 * r][x] = Wo[(size_t)(bds + y + 4 * r) * OD + bo + x];
        __syncthreads();
        #pragma unroll
        for (int r = 0; r < 8; r++) {
            const int o = bo + y + 4 * r;
            const int d = bds + x;
            T[(size_t)o * DD + d] = __float2half_rn(tile[x][y + 4 * r]);
        }
        __syncthreads();
    }
}

// Fused first stage:
//   z=0 -> h = relu(text@Wa1+ba1)
//   z=1 -> outx = image@Wx+bx (+ fp16 copy outxh)
//   z=2 -> WoT = fp16(Wo^T)   (independent, rides along)
__global__ void __launch_bounds__(128)
pre_fused_kernel(const float* __restrict__ text, const float* __restrict__ image,
                 const float* __restrict__ Wa1, const float* __restrict__ ba1,
                 const float* __restrict__ Wx,  const float* __restrict__ bx,
                 const float* __restrict__ Wo,
                 float* __restrict__ h, float* __restrict__ outx,
                 __half* __restrict__ outxh, __half* __restrict__ wot)
{
    if (blockIdx.z == 0)
        gemm_small_body<1, false>(text, Wa1, ba1, h, nullptr, blockIdx.y * 64, blockIdx.x * 32);
    else if (blockIdx.z == 1)
        gemm_small_body<0, true>(image, Wx, bx, outx, outxh, blockIdx.y * 64, blockIdx.x * 32);
    else
        transpose_wo_body(Wo, wot, blockIdx.x * 32, blockIdx.y * 64);
}

// ============================================================
// Preamble: row softmax * text
// ============================================================
__global__ void __launch_bounds__(512)
softmax_mul_kernel(const float* __restrict__ logits, const float* __restrict__ text,
                   float* __restrict__ out)
{
    __shared__ float sdata[512];
    const int row = blockIdx.x, t = threadIdx.x;
    const float v = logits[(size_t)row * DD + t];
    sdata[t] = v; __syncthreads();
    for (int s = 256; s > 0; s >>= 1) { if (t < s) sdata[t] = fmaxf(sdata[t], sdata[t + s]); __syncthreads(); }
    const float mx = sdata[0]; __syncthreads();
    const float e = __expf(v - mx);
    sdata[t] = e; __syncthreads();
    for (int s = 256; s > 0; s >>= 1) { if (t < s) sdata[t] += sdata[t + s]; __syncthreads(); }
    out[(size_t)row * DD + t] = e * (1.0f / sdata[0]) * text[(size_t)row * DD + t];
}

__global__ void mul_kernel(const float* __restrict__ a, const float* __restrict__ b,
                           float* __restrict__ c, int n)
{
    int idx = blockIdx.x * blockDim.x + threadIdx.x;
    if (idx < n) c[idx] = a[idx] * b[idx];
}

// ============================================================
// Big einsum, fp16 HMMA, 2 i/CTA with register-pipelined
// fragment loads (R14, best: 599.9us). UNCHANGED.
// grid (4 o, 4 j, 256 i-pairs), 256 threads (8 warps).
// ============================================================
__global__ void __launch_bounds__(256, 1)
big_einsum_hmma_kernel(const __half* __restrict__ outxh, const float* __restrict__ gate,
                       const float* __restrict__ bo, float* __restrict__ out)
{
    extern __shared__ char dynsmem[];
    float* gs = (float*)dynsmem;   // [0..511]=gate(i0), [512..1023]=gate(i1)
    const uint32_t sbase = smem_u32(dynsmem) + 4096u;

    const int i0 = blockIdx.z * 2;
    const int j0 = blockIdx.y * 128;
    const int o0 = blockIdx.x * 128;
    const int tid  = threadIdx.x;
    const int wid  = tid >> 5;
    const int lane = tid & 31;
    const int warp_m = wid & 3;     // 4 x 32 rows (j)
    const int warp_n = wid >> 2;    // 2 x 64 cols (o)

    gs[tid]        = gate[(size_t)i0 * DD + tid];
    gs[tid + 256]  = gate[(size_t)i0 * DD + tid + 256];
    gs[tid + 512]  = gate[(size_t)(i0 + 1) * DD + tid];
    gs[tid + 768]  = gate[(size_t)(i0 + 1) * DD + tid + 256];

    const int arow = tid >> 1;
    const int ach  = (tid & 1) * 32;

    auto cpB = [&](int c, int buf) {
        const int c0 = c * 64;
        const uint32_t bdst = sbase + buf * BUF_BYTES + OFF_B;
        #pragma unroll
        for (int q = 0; q < 4; q++) {
            const int g   = tid + q * 256;
            const int row = g >> 3;
            const int ck  = g & 7;
            const uint32_t dso = (uint32_t)(row * ASTRIDE + ck * 16);
            const __half* src = g_WoT + (size_t)(o0 + row) * DD + c0 + ck * 8;
            CP_ASYNC_16(bdst + dso, src);
        }
        CP_ASYNC_COMMIT();
    };

    uint4 av[4];
    auto loadA = [&](int c) {
        const __half* p = outxh + (size_t)(j0 + arow) * DD + c * 64 + ach;
        #pragma unroll
        for (int q = 0; q < 4; q++) av[q] = __ldg((const uint4*)(p + q * 8));
    };

    auto storeA = [&](int c, int buf) {
        const int d0 = c * 64 + ach;
        #pragma unroll
        for (int iv = 0; iv < 2; iv++) {
            const uint32_t ad = sbase + buf * BUF_BYTES
                              + (iv ? OFF_A1 : OFF_A0) + arow * ASTRIDE + ach * 2;
            const float* gp = gs + iv * 512 + d0;
            #pragma unroll
            for (int h = 0; h < 4; h++) {
                const __half2* xa = (const __half2*)&av[h];
                uint32_t w[4];
                #pragma unroll
                for (int q = 0; q < 4; q++) {
                    float2 xf = __half22float2(xa[q]);
                    const float2 gf = *(const float2*)&gp[h * 8 + q * 2];
                    __half2 r = __float22half2_rn(make_float2(xf.x * gf.x, xf.y * gf.y));
                    w[q] = *(uint32_t*)&r;
                }
                asm volatile("st.shared.v4.b32 [%0], {%1,%2,%3,%4};"
                             :: "r"(ad + h * 16), "r"(w[0]), "r"(w[1]), "r"(w[2]), "r"(w[3]));
            }
        }
    };

    const uint32_t a_lane = (uint32_t)(((lane & 7) + ((lane >> 3) & 1) * 8) * ASTRIDE
                                       + (lane >> 4) * 16);
    const uint32_t b_lane = (uint32_t)(((lane & 7) + (lane >> 4) * 8) * ASTRIDE
                                       + ((lane >> 3) & 1) * 16);
    const uint32_t a_warp = (uint32_t)(warp_m * 32 * ASTRIDE);
    const uint32_t b_warp = (uint32_t)(warp_n * 64 * ASTRIDE);

    float acc0[2][8][4] = {};
    float acc1[2][8][4] = {};

    loadA(0);
    cpB(0, 0);
    __syncthreads();
    storeA(0, 0);
    CP_ASYNC_WAIT0();
    __syncthreads();

    for (int c = 0; c < 8; c++) {
        const int buf = c & 1;
        if (c < 7) { loadA(c + 1); cpB(c + 1, buf ^ 1); }

        const uint32_t bb = sbase + buf * BUF_BYTES;

        uint32_t a0c[2][4], a1c[2][4], bhc[4];
        #pragma unroll
        for (int mt = 0; mt < 2; mt++) {
            ldsm_x4(a0c[mt], bb + OFF_A0 + a_warp + a_lane + mt * 16 * ASTRIDE);
            ldsm_x4(a1c[mt], bb + OFF_A1 + a_warp + a_lane + mt * 16 * ASTRIDE);
        }
        ldsm_x4(bhc, bb + OFF_B + b_warp + b_lane);

        #pragma unroll
        for (int ks = 0; ks < 4; ks++) {
            uint32_t a0n[2][4], a1n[2][4];
            #pragma unroll
            for (int g = 0; g < 4; g++) {
                uint32_t bhn[4];
                if (g < 3) {
                    ldsm_x4(bhn, bb + OFF_B + b_warp + b_lane
                                  + (g + 1) * 16 * ASTRIDE + ks * 32);
                } else if (ks < 3) {
                    #pragma unroll
                    for (int mt = 0; mt < 2; mt++) {
                        ldsm_x4(a0n[mt], bb + OFF_A0 + a_warp + a_lane
                                          + mt * 16 * ASTRIDE + (ks + 1) * 32);
                        ldsm_x4(a1n[mt], bb + OFF_A1 + a_warp + a_lane
                                          + mt * 16 * ASTRIDE + (ks + 1) * 32);
                    }
                    ldsm_x4(bhn, bb + OFF_B + b_warp + b_lane + (ks + 1) * 32);
                }
                #pragma unroll
                for (int mt = 0; mt < 2; mt++) {
                    mma_fp16(acc0[mt][g * 2],     a0c[mt], bhc[0], bhc[1]);
                    mma_fp16(acc0[mt][g * 2 + 1], a0c[mt], bhc[2], bhc[3]);
                    mma_fp16(acc1[mt][g * 2],     a1c[mt], bhc[0], bhc[1]);
                    mma_fp16(acc1[mt][g * 2 + 1], a1c[mt], bhc[2], bhc[3]);
                }
                if (g < 3 || ks < 3) {
                    #pragma unroll
                    for (int q = 0; q < 4; q++) bhc[q] = bhn[q];
                }
            }
            if (ks < 3) {
                #pragma unroll
                for (int mt = 0; mt < 2; mt++)
                    #pragma unroll
                    for (int q = 0; q < 4; q++) {
                        a0c[mt][q] = a0n[mt][q];
                        a1c[mt][q] = a1n[mt][q];
                    }
            }
        }

        if (c < 7) {
            storeA(c + 1, buf ^ 1);
            CP_ASYNC_WAIT0();
            __syncthreads();
        }
    }

    const int colb = o0 + warp_n * 64 + (lane & 3) * 2;
    float2 bv[8];
    #pragma unroll
    for (int nj = 0; nj < 8; nj++)
        bv[nj] = __ldg((const float2*)&bo[colb + nj * 8]);

    const int rowb = j0 + warp_m * 32 + (lane >> 2);
    #pragma unroll
    for (int iv = 0; iv < 2; iv++) {
        #pragma unroll
        for (int mt = 0; mt < 2; mt++) {
            #pragma unroll
            for (int h = 0; h < 2; h++) {
                const size_t rbase = ((size_t)(i0 + iv) * NB + (rowb + mt * 16 + h * 8)) * OD;
                #pragma unroll
                for (int nj = 0; nj < 8; nj++) {
                    const float* a = iv ? acc1[mt][nj] : acc0[mt][nj];
                    float2 v;
                    v.x = a[h * 2]     + bv[nj].x;
                    v.y = a[h * 2 + 1] + bv[nj].y;
                    *(float2*)&out[rbase + colb + nj * 8] = v;
                }
            }
        }
    }
}

// ============================================================
// kernel_launch
// ============================================================
extern "C" void kernel_launch(void* const* d_in, const int* in_sizes, int n_in,
                              void* d_out, int out_size)
{
    const float* image = (const float*)d_in[0];
    const float* text  = (const float*)d_in[1];
    const float* Wx  = (const float*)d_in[3];
    const float* bx  = (const float*)d_in[4];
    const float* Wy  = (const float*)d_in[5];
    const float* by  = (const float*)d_in[6];
    const float* Wo  = (const float*)d_in[7];
    const float* bo  = (const float*)d_in[8];
    const float* Wa1 = (const float*)d_in[9];
    const float* ba1 = (const float*)d_in[10];
    const float* Wa2 = (const float*)d_in[11];
    const float* ba2 = (const float*)d_in[12];
    float* out = (float*)d_out;

    float *h, *logits, *textw, *outx, *gate, *tmp;
    __half *wot, *outxh;
    cudaGetSymbolAddress((void**)&h,      g_h);
    cudaGetSymbolAddress((void**)&logits, g_logits);
    cudaGetSymbolAddress((void**)&textw,  g_textw);
    cudaGetSymbolAddress((void**)&outx,   g_outx);
    cudaGetSymbolAddress((void**)&gate,   g_gate);
    cudaGetSymbolAddress((void**)&tmp,    g_tmp);
    cudaGetSymbolAddress((void**)&wot,    g_WoT);
    cudaGetSymbolAddress((void**)&outxh,  g_outxh);

    cudaFuncSetAttribute(big_einsum_hmma_kernel,
                         cudaFuncAttributeMaxDynamicSharedMemorySize, SMEM_BYTES);

    const dim3 gsm(OD / 32, NB / 64);   // (16, 8) = 128 CTAs

    // Stage 1 fused: h, outx(+outxh), WoT transpose — one launch
    pre_fused_kernel<<<dim3(OD / 32, NB / 64, 3), 128>>>(text, image, Wa1, ba1, Wx, bx,
                                                         Wo, h, outx, outxh, wot);
    // logits = h@Wa2+ba2
    gemm_small_kernel<0><<<gsm, 128>>>(h, Wa2, ba2, logits);
    // textw = softmax(logits) * text
    softmax_mul_kernel<<<NB, 512>>>(logits, text, textw);
    // gate = sigmoid(textw@Wy+by)
    gemm_small_kernel<2><<<gsm, 128>>>(textw, Wy, by, gate);

    if (out_size == NB * NB * OD) {
        dim3 grid(OD / 128, NB / 128, NB / 2);   // (4, 4, 256)
        big_einsum_hmma_kernel<<<grid, 256, SMEM_BYTES>>>(outxh, gate, bo, out);
    } else {
        mul_kernel<<<(NB * DD + 255) / 256, 256>>>(gate, outx, tmp, NB * DD);
        gemm_small_kernel<0><<<gsm, 128>>>(tmp, Wo, bo, out);
    }
}